// round 1
// baseline (speedup 1.0000x reference)
#include <cuda_runtime.h>
#include <math.h>

// Problem constants
#define BATCH 32
#define HDIM  14
#define WDIM  14
#define CDIM  32
#define KSZ   5
#define KOUT  64
#define OHW   10          // output spatial dim (14-5+1)
#define PDIM  100         // OHW*OHW
#define NROWS (BATCH*PDIM)   // 3200
#define MDIM  (KSZ*KSZ*CDIM) // 800
#define NPIX  (HDIM*WDIM)    // 196

#define MU_OUT_ELEMS (BATCH*OHW*OHW*KOUT)   // 204800

// scratch: diag_vals[b*100+p][k]
__device__ float g_diag_vals[NROWS * KOUT];

// ---------------------------------------------------------------------------
// Kernel 1: fused conv.  Computes
//   mu_out[r,k]    = sum_m muP[r,m] * w[m,k]
//   diag_vals[r,k] = sum_m dsg[r,m] * w[m,k]^2 + softplus(w_sigma[k]) * sum_m dsg[r,m]
// where r = b*100 + p, m = (i*5+j)*32 + c,
//   muP[r,m] = mu_in[b, ph+i, pw+j, c],
//   dsg[r,m] = Sigma_in[b, n, n, c] with n = (ph+i)*14 + (pw+j)  (diagonal gather)
//
// grid = 100 blocks (32 rows each), 128 threads = (tx:16 k-groups) x (ty:8 row-groups)
// thread tile: 4 rows (ty+8u) x 4 k (tx+16v), dual accumulators.
// ---------------------------------------------------------------------------
__global__ __launch_bounds__(128) void conv_fused_kernel(
    const float* __restrict__ mu_in,
    const float* __restrict__ Sigma_in,
    const float* __restrict__ w_mu,
    const float* __restrict__ w_sigma,
    float* __restrict__ mu_out)
{
    __shared__ float shA[32][33];     // mu patch slice  [row][c]
    __shared__ float shD[32][33];     // diag patch slice
    __shared__ float shW[32 * 64];    // w slice [c][k]
    __shared__ float shTr[32];

    const int t  = threadIdx.x;
    const int tx = t & 15;            // k group
    const int ty = t >> 4;            // row group 0..7
    const int r0 = blockIdx.x * 32;

    float accM[4][4] = {};
    float accV[4][4] = {};
    float trAcc[4]   = {0.f, 0.f, 0.f, 0.f};

    for (int slice = 0; slice < 25; slice++) {
        const int i = slice / 5;
        const int j = slice % 5;
        __syncthreads();
        // load A/D tiles: 32 rows x 32 c, 8 elements per thread
        {
            const int c  = t & 31;
            const int rb = t >> 5;    // 0..3
            #pragma unroll
            for (int s = 0; s < 8; s++) {
                const int r   = rb + 4 * s;       // 0..31
                const int row = r0 + r;
                const int b   = row / 100;
                const int p   = row - b * 100;
                const int y   = p / 10 + i;
                const int x   = p - (p / 10) * 10 + j;
                shA[r][c] = mu_in[((b * HDIM + y) * WDIM + x) * CDIM + c];
                const int n = y * WDIM + x;
                shD[r][c] = Sigma_in[(size_t)((b * NPIX + n) * NPIX + n) * CDIM + c];
            }
            // load W slice: 32x64 elements, 16 per thread (coalesced)
            const float* wsl = w_mu + slice * 32 * 64;
            #pragma unroll
            for (int s = 0; s < 16; s++) {
                const int idx = t + 128 * s;
                shW[idx] = wsl[idx];
            }
        }
        __syncthreads();
        #pragma unroll 4
        for (int c = 0; c < 32; c++) {
            float a[4], d[4], w[4], wsq[4];
            #pragma unroll
            for (int u = 0; u < 4; u++) { a[u] = shA[ty + 8 * u][c]; d[u] = shD[ty + 8 * u][c]; }
            #pragma unroll
            for (int v = 0; v < 4; v++) { w[v] = shW[c * 64 + tx + 16 * v]; wsq[v] = w[v] * w[v]; }
            #pragma unroll
            for (int u = 0; u < 4; u++)
                #pragma unroll
                for (int v = 0; v < 4; v++) {
                    accM[u][v] = fmaf(a[u], w[v],   accM[u][v]);
                    accV[u][v] = fmaf(d[u], wsq[v], accV[u][v]);
                }
            if (tx == 0) {
                #pragma unroll
                for (int u = 0; u < 4; u++) trAcc[u] += d[u];
            }
        }
    }
    __syncthreads();
    if (tx == 0) {
        #pragma unroll
        for (int u = 0; u < 4; u++) shTr[ty + 8 * u] = trAcc[u];
    }
    __syncthreads();

    #pragma unroll
    for (int u = 0; u < 4; u++) {
        const int r  = r0 + ty + 8 * u;
        const float tr = shTr[ty + 8 * u];
        #pragma unroll
        for (int v = 0; v < 4; v++) {
            const int k = tx + 16 * v;
            const float sp = log1pf(expf(w_sigma[k]));
            mu_out[r * KOUT + k]      = accM[u][v];
            g_diag_vals[r * KOUT + k] = accV[u][v] + sp * tr;
        }
    }
}

// ---------------------------------------------------------------------------
// Kernel 2: fused Gram + Sigma_out writer.
//   G[b,p,q] = sum_m muP[b,p,m] * muP[b,q,m]
//   Sigma_out[b,p,q,k] = sp[k]*G + (p==q ? diag_vals[b,p,k] : 0)
//   then zero non-finite, then abs at (q==k).
// grid = (4 tiles, 32 b): tile index = pt*2+qt, tiles 64x64 over 100x100 (masked).
// 256 threads = 16x16; thread tile 4x4 (rows ty+16u, cols tx+16v).
// ---------------------------------------------------------------------------
__global__ __launch_bounds__(256) void sigma_kernel(
    const float* __restrict__ mu_in,
    const float* __restrict__ w_sigma,
    float* __restrict__ sig_out)
{
    __shared__ float shP[64][33];
    __shared__ float shQ[64][33];
    __shared__ __align__(16) float shSp[64];

    const int b  = blockIdx.y;
    const int pt = blockIdx.x >> 1;
    const int qt = blockIdx.x & 1;
    const int p0 = pt * 64;
    const int q0 = qt * 64;
    const int t  = threadIdx.x;
    const int tx = t & 15;
    const int ty = t >> 4;

    if (t < 64) shSp[t] = log1pf(expf(w_sigma[t]));

    float acc[4][4] = {};

    const float* mub = mu_in + (size_t)b * (HDIM * WDIM * CDIM);

    for (int slice = 0; slice < 25; slice++) {
        const int i = slice / 5;
        const int j = slice % 5;
        __syncthreads();
        {
            const int c  = t & 31;
            const int rb = t >> 5;    // 0..7
            #pragma unroll
            for (int s = 0; s < 8; s++) {
                const int r = rb + 8 * s;   // 0..63
                const int p = p0 + r;
                const int q = q0 + r;
                float vp = 0.f, vq = 0.f;
                if (p < PDIM) {
                    const int y = p / 10 + i, x = p % 10 + j;
                    vp = mub[(y * WDIM + x) * CDIM + c];
                }
                if (q < PDIM) {
                    const int y = q / 10 + i, x = q % 10 + j;
                    vq = mub[(y * WDIM + x) * CDIM + c];
                }
                shP[r][c] = vp;
                shQ[r][c] = vq;
            }
        }
        __syncthreads();
        #pragma unroll 4
        for (int c = 0; c < 32; c++) {
            float a[4], bq[4];
            #pragma unroll
            for (int u = 0; u < 4; u++) a[u]  = shP[ty + 16 * u][c];
            #pragma unroll
            for (int v = 0; v < 4; v++) bq[v] = shQ[tx + 16 * v][c];
            #pragma unroll
            for (int u = 0; u < 4; u++)
                #pragma unroll
                for (int v = 0; v < 4; v++)
                    acc[u][v] = fmaf(a[u], bq[v], acc[u][v]);
        }
    }
    __syncthreads();

    // expansion + write: 64 k-values per G entry
    #pragma unroll
    for (int u = 0; u < 4; u++) {
        const int p = p0 + ty + 16 * u;
        if (p >= PDIM) continue;
        const float4* dgrow = reinterpret_cast<const float4*>(&g_diag_vals[(b * PDIM + p) * KOUT]);
        #pragma unroll
        for (int v = 0; v < 4; v++) {
            const int q = q0 + tx + 16 * v;
            if (q >= PDIM) continue;
            const float g = acc[u][v];
            float4* outp = reinterpret_cast<float4*>(
                sig_out + ((size_t)(b * PDIM + p) * PDIM + q) * KOUT);
            const bool diag = (p == q);
            const int  qk4  = q >> 2;   // float4 index that contains k==q (only if q<64)
            const int  qc   = q & 3;
            #pragma unroll
            for (int k4 = 0; k4 < 16; k4++) {
                const float4 s = reinterpret_cast<const float4*>(shSp)[k4];
                float4 o;
                o.x = s.x * g; o.y = s.y * g; o.z = s.z * g; o.w = s.w * g;
                if (diag) {
                    const float4 dv = dgrow[k4];
                    o.x += dv.x; o.y += dv.y; o.z += dv.z; o.w += dv.w;
                }
                // zero non-finite (reference semantics)
                o.x = isfinite(o.x) ? o.x : 0.f;
                o.y = isfinite(o.y) ? o.y : 0.f;
                o.z = isfinite(o.z) ? o.z : 0.f;
                o.w = isfinite(o.w) ? o.w : 0.f;
                if (k4 == qk4) {   // k == q component gets abs
                    if      (qc == 0) o.x = fabsf(o.x);
                    else if (qc == 1) o.y = fabsf(o.y);
                    else if (qc == 2) o.z = fabsf(o.z);
                    else              o.w = fabsf(o.w);
                }
                outp[k4] = o;
            }
        }
    }
}

// ---------------------------------------------------------------------------
extern "C" void kernel_launch(void* const* d_in, const int* in_sizes, int n_in,
                              void* d_out, int out_size)
{
    const float* mu_in    = (const float*)d_in[0];
    const float* Sigma_in = (const float*)d_in[1];
    const float* w_mu     = (const float*)d_in[2];
    const float* w_sigma  = (const float*)d_in[3];
    float* out = (float*)d_out;

    // mu_out occupies [0, 204800), Sigma_out occupies the rest.
    conv_fused_kernel<<<NROWS / 32, 128>>>(mu_in, Sigma_in, w_mu, w_sigma, out);
    sigma_kernel<<<dim3(4, BATCH), 256>>>(mu_in, w_sigma, out + MU_OUT_ELEMS);
}

// round 4
// speedup vs baseline: 1.3510x; 1.3510x over previous
#include <cuda_runtime.h>
#include <math.h>

// Problem constants
#define BATCH 32
#define HDIM  14
#define WDIM  14
#define CDIM  32
#define KSZ   5
#define KOUT  64
#define OHW   10
#define PDIM  100
#define NROWS (BATCH*PDIM)     // 3200
#define NPIX  (HDIM*WDIM)      // 196
#define MU_OUT_ELEMS (BATCH*OHW*OHW*KOUT)   // 204800

// scratch
__device__ float g_diag_vals[NROWS * KOUT];          // [b*100+p][k]
__device__ float g_G[BATCH * PDIM * PDIM];           // [b][p][q]

// ---------------------------------------------------------------------------
// Kernel 1: fused conv (mu path + variance diag path).
// grid 200 x 128 threads; 16 rows/block; thread = 2 rows (ty, ty+8) x 4 k (tx*4).
// smem is c-major so weight reads are LDS.128 and a/d reads broadcast.
// Register prefetch of the next (i,j) slice overlaps the FMA loop.
// ---------------------------------------------------------------------------
__global__ __launch_bounds__(128) void conv_kernel(
    const float* __restrict__ mu_in,
    const float* __restrict__ Sigma_in,
    const float* __restrict__ w_mu,
    const float* __restrict__ w_sigma,
    float* __restrict__ mu_out)
{
    __shared__ float shA[2][CDIM * 16];      // [c][r]
    __shared__ float shD[2][CDIM * 16];
    __shared__ float shW[2][CDIM * KOUT];    // [c][k]
    __shared__ float shTr[16];

    const int t  = threadIdx.x;
    const int tx = t & 15;
    const int ty = t >> 4;
    const int r0 = blockIdx.x * 16;

    // loader mapping: 16 rows x 32 c, one float4 of c per thread
    const int lr = t >> 3;
    const int lc = (t & 7) * 4;
    const int lrow = r0 + lr;
    const int lb   = lrow / 100;
    const int lp   = lrow - lb * 100;
    const int lpy  = lp / 10;
    const int lpx  = lp - lpy * 10;

    float4 pA, pD, pW0, pW1, pW2, pW3;

    // ---- prefetch slice 0
    {
        const int y = lpy, x = lpx;
        pA = *(const float4*)(mu_in + (((lb * HDIM + y) * WDIM + x) * CDIM) + lc);
        const int n = y * WDIM + x;
        pD = *(const float4*)(Sigma_in + (size_t)(lb * NPIX + n) * (NPIX * CDIM)
                              + (size_t)n * CDIM + lc);
        const float4* wsl = (const float4*)(w_mu);
        pW0 = wsl[t]; pW1 = wsl[t + 128]; pW2 = wsl[t + 256]; pW3 = wsl[t + 384];
    }
    // ---- stage slice 0 into buffer 0
    {
        shA[0][(lc + 0) * 16 + lr] = pA.x;
        shA[0][(lc + 1) * 16 + lr] = pA.y;
        shA[0][(lc + 2) * 16 + lr] = pA.z;
        shA[0][(lc + 3) * 16 + lr] = pA.w;
        shD[0][(lc + 0) * 16 + lr] = pD.x;
        shD[0][(lc + 1) * 16 + lr] = pD.y;
        shD[0][(lc + 2) * 16 + lr] = pD.z;
        shD[0][(lc + 3) * 16 + lr] = pD.w;
        float4* w4 = (float4*)shW[0];
        w4[t] = pW0; w4[t + 128] = pW1; w4[t + 256] = pW2; w4[t + 384] = pW3;
    }
    __syncthreads();

    float accM[2][4] = {};
    float accV[2][4] = {};
    float tr0 = 0.f, tr1 = 0.f;

    for (int s = 0; s < 25; s++) {
        const int buf = s & 1;
        if (s < 24) {
            const int sl = s + 1;
            const int i = sl / 5, j = sl % 5;
            const int y = lpy + i, x = lpx + j;
            pA = *(const float4*)(mu_in + (((lb * HDIM + y) * WDIM + x) * CDIM) + lc);
            const int n = y * WDIM + x;
            pD = *(const float4*)(Sigma_in + (size_t)(lb * NPIX + n) * (NPIX * CDIM)
                                  + (size_t)n * CDIM + lc);
            const float4* wsl = (const float4*)(w_mu + sl * (CDIM * KOUT));
            pW0 = wsl[t]; pW1 = wsl[t + 128]; pW2 = wsl[t + 256]; pW3 = wsl[t + 384];
        }

        #pragma unroll 8
        for (int c = 0; c < CDIM; c++) {
            const float a0 = shA[buf][c * 16 + ty];
            const float a1 = shA[buf][c * 16 + ty + 8];
            const float d0 = shD[buf][c * 16 + ty];
            const float d1 = shD[buf][c * 16 + ty + 8];
            const float4 w4 = *(const float4*)&shW[buf][c * KOUT + tx * 4];
            const float w0 = w4.x, w1 = w4.y, w2 = w4.z, w3 = w4.w;
            accM[0][0] = fmaf(a0, w0, accM[0][0]);
            accM[0][1] = fmaf(a0, w1, accM[0][1]);
            accM[0][2] = fmaf(a0, w2, accM[0][2]);
            accM[0][3] = fmaf(a0, w3, accM[0][3]);
            accM[1][0] = fmaf(a1, w0, accM[1][0]);
            accM[1][1] = fmaf(a1, w1, accM[1][1]);
            accM[1][2] = fmaf(a1, w2, accM[1][2]);
            accM[1][3] = fmaf(a1, w3, accM[1][3]);
            accV[0][0] = fmaf(d0, w0 * w0, accV[0][0]);
            accV[0][1] = fmaf(d0, w1 * w1, accV[0][1]);
            accV[0][2] = fmaf(d0, w2 * w2, accV[0][2]);
            accV[0][3] = fmaf(d0, w3 * w3, accV[0][3]);
            accV[1][0] = fmaf(d1, w0 * w0, accV[1][0]);
            accV[1][1] = fmaf(d1, w1 * w1, accV[1][1]);
            accV[1][2] = fmaf(d1, w2 * w2, accV[1][2]);
            accV[1][3] = fmaf(d1, w3 * w3, accV[1][3]);
            if (tx == 0) { tr0 += d0; tr1 += d1; }
        }

        if (s < 24) {
            const int nb = (s + 1) & 1;
            shA[nb][(lc + 0) * 16 + lr] = pA.x;
            shA[nb][(lc + 1) * 16 + lr] = pA.y;
            shA[nb][(lc + 2) * 16 + lr] = pA.z;
            shA[nb][(lc + 3) * 16 + lr] = pA.w;
            shD[nb][(lc + 0) * 16 + lr] = pD.x;
            shD[nb][(lc + 1) * 16 + lr] = pD.y;
            shD[nb][(lc + 2) * 16 + lr] = pD.z;
            shD[nb][(lc + 3) * 16 + lr] = pD.w;
            float4* w4 = (float4*)shW[nb];
            w4[t] = pW0; w4[t + 128] = pW1; w4[t + 256] = pW2; w4[t + 384] = pW3;
        }
        __syncthreads();
    }

    if (tx == 0) { shTr[ty] = tr0; shTr[ty + 8] = tr1; }
    __syncthreads();

    float sp[4];
    #pragma unroll
    for (int v = 0; v < 4; v++) sp[v] = log1pf(expf(w_sigma[tx * 4 + v]));

    #pragma unroll
    for (int u = 0; u < 2; u++) {
        const int r  = r0 + ty + 8 * u;
        const float tr = shTr[ty + 8 * u];
        float4 m4 = make_float4(accM[u][0], accM[u][1], accM[u][2], accM[u][3]);
        float4 v4 = make_float4(accV[u][0] + sp[0] * tr, accV[u][1] + sp[1] * tr,
                                accV[u][2] + sp[2] * tr, accV[u][3] + sp[3] * tr);
        *(float4*)(mu_out + r * KOUT + tx * 4)      = m4;
        *(float4*)(g_diag_vals + r * KOUT + tx * 4) = v4;
    }
}

// ---------------------------------------------------------------------------
// Kernel 2: Gram matrix G[b,p,q] = sum_m muP[p,m]*muP[q,m] -> scratch.
// grid (4 tiles, 32 b), 256 threads (16x16), thread tile 4x4 (consecutive ->
// LDS.128 on both operands). Single-buffered (compute dominates at 64x64x32).
// ---------------------------------------------------------------------------
__global__ __launch_bounds__(256) void gram_kernel(
    const float* __restrict__ mu_in)
{
    __shared__ float shP[CDIM * 64];   // [c][r]
    __shared__ float shQ[CDIM * 64];

    const int b  = blockIdx.y;
    const int p0 = (blockIdx.x >> 1) * 64;
    const int q0 = (blockIdx.x & 1) * 64;
    const int t  = threadIdx.x;
    const int tx = t & 15;
    const int ty = t >> 4;

    const float* mub = mu_in + (size_t)b * (HDIM * WDIM * CDIM);

    float acc[4][4] = {};

    for (int s = 0; s < 25; s++) {
        const int i = s / 5, j = s % 5;
        __syncthreads();
        // loader: 64 rows x 32 c per side; 2 float4 per thread per side
        #pragma unroll
        for (int e0 = 0; e0 < 2; e0++) {
            const int e  = t + 256 * e0;      // float4 index 0..511
            const int r  = e >> 3;
            const int cb = (e & 7) * 4;
            const int p = p0 + r, q = q0 + r;
            float4 vp = make_float4(0.f, 0.f, 0.f, 0.f);
            float4 vq = vp;
            if (p < PDIM) {
                const int y = p / 10 + i, x = p % 10 + j;
                vp = *(const float4*)(mub + (y * WDIM + x) * CDIM + cb);
            }
            if (q < PDIM) {
                const int y = q / 10 + i, x = q % 10 + j;
                vq = *(const float4*)(mub + (y * WDIM + x) * CDIM + cb);
            }
            shP[(cb + 0) * 64 + r] = vp.x;
            shP[(cb + 1) * 64 + r] = vp.y;
            shP[(cb + 2) * 64 + r] = vp.z;
            shP[(cb + 3) * 64 + r] = vp.w;
            shQ[(cb + 0) * 64 + r] = vq.x;
            shQ[(cb + 1) * 64 + r] = vq.y;
            shQ[(cb + 2) * 64 + r] = vq.z;
            shQ[(cb + 3) * 64 + r] = vq.w;
        }
        __syncthreads();

        #pragma unroll 8
        for (int c = 0; c < CDIM; c++) {
            const float4 a4 = *(const float4*)&shP[c * 64 + ty * 4];
            const float4 b4 = *(const float4*)&shQ[c * 64 + tx * 4];
            const float a0 = a4.x, a1 = a4.y, a2 = a4.z, a3 = a4.w;
            const float b0 = b4.x, b1 = b4.y, b2 = b4.z, b3 = b4.w;
            acc[0][0] = fmaf(a0, b0, acc[0][0]);
            acc[0][1] = fmaf(a0, b1, acc[0][1]);
            acc[0][2] = fmaf(a0, b2, acc[0][2]);
            acc[0][3] = fmaf(a0, b3, acc[0][3]);
            acc[1][0] = fmaf(a1, b0, acc[1][0]);
            acc[1][1] = fmaf(a1, b1, acc[1][1]);
            acc[1][2] = fmaf(a1, b2, acc[1][2]);
            acc[1][3] = fmaf(a1, b3, acc[1][3]);
            acc[2][0] = fmaf(a2, b0, acc[2][0]);
            acc[2][1] = fmaf(a2, b1, acc[2][1]);
            acc[2][2] = fmaf(a2, b2, acc[2][2]);
            acc[2][3] = fmaf(a2, b3, acc[2][3]);
            acc[3][0] = fmaf(a3, b0, acc[3][0]);
            acc[3][1] = fmaf(a3, b1, acc[3][1]);
            acc[3][2] = fmaf(a3, b2, acc[3][2]);
            acc[3][3] = fmaf(a3, b3, acc[3][3]);
        }
    }

    float* Gb = g_G + (size_t)b * (PDIM * PDIM);
    #pragma unroll
    for (int u = 0; u < 4; u++) {
        const int p = p0 + ty * 4 + u;
        if (p >= PDIM) continue;
        const int q = q0 + tx * 4;
        if (q >= PDIM) continue;   // q multiple of 4; q<=96 -> full float4 fits
        *(float4*)(Gb + p * PDIM + q) =
            make_float4(acc[u][0], acc[u][1], acc[u][2], acc[u][3]);
    }
}

// ---------------------------------------------------------------------------
// Kernel 3: expansion/writer. One block per (b,p) row.
//   Sigma_out[b,p,q,k] = sp[k]*G[b,p,q] + (q==p ? diag_vals[b,p,k] : 0)
//   abs at (q==k).
// 128 threads: k4 = t&15 fixed per thread (sp4/dg4 in regs), q = t>>4 + 8*s.
// Warp stores 512B contiguous per iteration.
// ---------------------------------------------------------------------------
__global__ __launch_bounds__(128) void expand_kernel(
    const float* __restrict__ w_sigma,
    float* __restrict__ sig_out)
{
    __shared__ __align__(16) float spS[KOUT];
    __shared__ __align__(16) float dgS[KOUT];
    __shared__ float gS[PDIM];

    const int bp = blockIdx.x;       // b*100 + p
    const int p  = bp % 100;
    const int t  = threadIdx.x;

    if (t < KOUT) {
        spS[t] = log1pf(expf(w_sigma[t]));
        dgS[t] = g_diag_vals[bp * KOUT + t];
    }
    if (t < PDIM) {
        const int b = bp / 100;
        gS[t] = g_G[(size_t)b * (PDIM * PDIM) + p * PDIM + t];
    }
    __syncthreads();

    const int k4  = t & 15;
    const int qo  = t >> 4;
    const float4 sp4 = ((const float4*)spS)[k4];
    const float4 dg4 = ((const float4*)dgS)[k4];

    float4* outBase = (float4*)(sig_out + (size_t)bp * (PDIM * KOUT));

    #pragma unroll
    for (int s = 0; s < 13; s++) {
        const int q = qo + 8 * s;
        if (q >= PDIM) break;
        const float g = gS[q];
        float4 o;
        o.x = sp4.x * g; o.y = sp4.y * g; o.z = sp4.z * g; o.w = sp4.w * g;
        if (q == p) { o.x += dg4.x; o.y += dg4.y; o.z += dg4.z; o.w += dg4.w; }
        if ((q >> 2) == k4) {          // k == q (implies q < 64)
            const int qc = q & 3;
            if      (qc == 0) o.x = fabsf(o.x);
            else if (qc == 1) o.y = fabsf(o.y);
            else if (qc == 2) o.z = fabsf(o.z);
            else              o.w = fabsf(o.w);
        }
        outBase[q * 16 + k4] = o;
    }
}

// ---------------------------------------------------------------------------
extern "C" void kernel_launch(void* const* d_in, const int* in_sizes, int n_in,
                              void* d_out, int out_size)
{
    const float* mu_in    = (const float*)d_in[0];
    const float* Sigma_in = (const float*)d_in[1];
    const float* w_mu     = (const float*)d_in[2];
    const float* w_sigma  = (const float*)d_in[3];
    float* out = (float*)d_out;

    conv_kernel<<<NROWS / 16, 128>>>(mu_in, Sigma_in, w_mu, w_sigma, out);
    gram_kernel<<<dim3(4, BATCH), 256>>>(mu_in);
    expand_kernel<<<NROWS, 128>>>(w_sigma, out + MU_OUT_ELEMS);
}